// round 4
// baseline (speedup 1.0000x reference)
#include <cuda_runtime.h>

// Problem constants (fixed: B=16, N=8192, C=256, num_points=2048)
#define BB   16
#define NN   8192
#define CC   256
#define MM   2048
#define TT   1024          // threads per FPS block
#define PPT  (NN / TT)     // points per thread = 8
#define NPAIR (PPT / 2)    // f32x2 pairs per thread = 4

// Scratch: selected indices, written by FPS kernel, read by gather kernel.
__device__ int g_idx[BB * MM];

// Dynamic smem: sq4[NN] (float4) + vslot[2] + fslot[2] + initv[32] + initi[32] + cent[96]
#define SMEM_BYTES (NN * 16 + 2 * 4 + 2 * 4 + 32 * 4 + 32 * 4 + 96 * 4)

// ---- packed f32x2 helpers (sm_103a) ---------------------------------------
__device__ __forceinline__ unsigned long long pack2(float lo, float hi) {
    unsigned long long r;
    asm("mov.b64 %0, {%1, %2};" : "=l"(r) : "f"(lo), "f"(hi));
    return r;
}
__device__ __forceinline__ void unpack2(unsigned long long v, float& lo, float& hi) {
    asm("mov.b64 {%0, %1}, %2;" : "=f"(lo), "=f"(hi) : "l"(v));
}
__device__ __forceinline__ unsigned long long add2(unsigned long long a, unsigned long long b) {
    unsigned long long r;
    asm("add.rn.f32x2 %0, %1, %2;" : "=l"(r) : "l"(a), "l"(b));
    return r;
}
__device__ __forceinline__ unsigned long long mul2(unsigned long long a, unsigned long long b) {
    unsigned long long r;
    asm("mul.rn.f32x2 %0, %1, %2;" : "=l"(r) : "l"(a), "l"(b));
    return r;
}
// ---------------------------------------------------------------------------

__device__ __forceinline__ float warp_sum(float x) {
    #pragma unroll
    for (int o = 16; o > 0; o >>= 1)
        x += __shfl_xor_sync(0xFFFFFFFFu, x, o);
    return x;
}

extern "C" __global__ void __launch_bounds__(TT, 1)
fps_kernel(const float* __restrict__ pts,   // [B, 3, N]
           float* __restrict__ out_pts)     // [B, M, 3]
{
    extern __shared__ unsigned char smraw[];
    float4*   sq4   = (float4*)smraw;                   // [NN] (x,y,z,_)
    unsigned* vslot = (unsigned*)(smraw + NN * 16);     // [2] block-max bits
    unsigned* fslot = vslot + 2;                        // [2] winning index
    unsigned* initv = fslot + 2;                        // [32]
    unsigned* initi = initv + 32;                       // [32]
    float*    cent  = (float*)(initi + 32);             // [96]

    const int b    = blockIdx.x;
    const int tid  = threadIdx.x;
    const int lane = tid & 31;
    const int warp = tid >> 5;

    const float* px = pts + (size_t)b * 3 * NN;
    const float* py = px + NN;
    const float* pz = px + 2 * NN;

    // Packed coords: pair j holds points (tid + 2j*TT, tid + (2j+1)*TT).
    unsigned long long X2[NPAIR], Y2[NPAIR], Z2[NPAIR];
    float dr[PPT];
    float s1 = 0.f, s2 = 0.f, s3 = 0.f;
    float xs[PPT], ys[PPT], zs[PPT];
    #pragma unroll
    for (int k = 0; k < PPT; k++) {
        int n = tid + k * TT;               // coalesced
        float x = px[n], y = py[n], z = pz[n];
        xs[k] = x; ys[k] = y; zs[k] = z;
        sq4[n] = make_float4(x, y, z, 0.f);
        s1 += x; s2 += y; s3 += z;
        dr[k] = 1e10f;
    }
    #pragma unroll
    for (int j = 0; j < NPAIR; j++) {
        X2[j] = pack2(xs[2 * j], xs[2 * j + 1]);
        Y2[j] = pack2(ys[2 * j], ys[2 * j + 1]);
        Z2[j] = pack2(zs[2 * j], zs[2 * j + 1]);
    }
    if (tid == 0) {
        vslot[0] = 0u; vslot[1] = 0u;
        fslot[0] = 0xFFFFFFFFu; fslot[1] = 0xFFFFFFFFu;
    }

    // Deterministic centroid (identical numerics to previous rounds).
    s1 = warp_sum(s1); s2 = warp_sum(s2); s3 = warp_sum(s3);
    if (lane == 0) { cent[warp] = s1; cent[32 + warp] = s2; cent[64 + warp] = s3; }
    __syncthreads();
    float cx = warp_sum(cent[lane])      * (1.0f / NN);
    float cy = warp_sum(cent[32 + lane]) * (1.0f / NN);
    float cz = warp_sum(cent[64 + lane]) * (1.0f / NN);

    // d0 = ||p - centroid||^2, initial farthest (one-shot; own scratch).
    float best = -1.0f; unsigned bi = 0;
    #pragma unroll
    for (int k = 0; k < PPT; k++) {
        float dx = xs[k] - cx, dy = ys[k] - cy, dz = zs[k] - cz;
        float d = __fadd_rn(__fadd_rn(__fmul_rn(dx, dx), __fmul_rn(dy, dy)),
                            __fmul_rn(dz, dz));
        if (d > best) { best = d; bi = (unsigned)(tid + k * TT); }
    }
    {
        unsigned vb = __float_as_uint(best);
        unsigned m1 = __reduce_max_sync(0xFFFFFFFFu, vb);
        unsigned c1 = (vb == m1) ? bi : 0xFFFFFFFFu;
        unsigned i1 = __reduce_min_sync(0xFFFFFFFFu, c1);
        if (lane == 0) { initv[warp] = m1; initi[warp] = i1; }
    }
    __syncthreads();
    unsigned far;
    {
        unsigned v2 = initv[lane];
        unsigned i2 = initi[lane];
        unsigned m2 = __reduce_max_sync(0xFFFFFFFFu, v2);
        unsigned c2 = (v2 == m2) ? i2 : 0xFFFFFFFFu;
        far = __reduce_min_sync(0xFFFFFFFFu, c2);
    }

    float* outp = out_pts + (size_t)b * MM * 3;
    int*   idxp = g_idx + b * MM;

    for (int m = 0; m < MM; m++) {
        const int buf = m & 1;
        // Broadcast the selected point's coords (one LDS.128, conflict-free).
        float4 q = sq4[far];
        if (tid == 0) {
            idxp[m] = (int)far;
            outp[m * 3 + 0] = q.x;
            outp[m * 3 + 1] = q.y;
            outp[m * 3 + 2] = q.z;
        }
        // Packed negated query (x - q == x + (-q), exact).
        unsigned long long nqx2 = pack2(-q.x, -q.x);
        unsigned long long nqy2 = pack2(-q.y, -q.y);
        unsigned long long nqz2 = pack2(-q.z, -q.z);

        float mx = -1.0f;
        #pragma unroll
        for (int j = 0; j < NPAIR; j++) {
            unsigned long long dx2 = add2(X2[j], nqx2);
            unsigned long long dy2 = add2(Y2[j], nqy2);
            unsigned long long dz2 = add2(Z2[j], nqz2);
            // d = (dx*dx + dy*dy) + dz*dz, RN per lane, no contraction:
            unsigned long long d2 = add2(add2(mul2(dx2, dx2), mul2(dy2, dy2)),
                                         mul2(dz2, dz2));
            float dlo, dhi;
            unpack2(d2, dlo, dhi);
            float nd0 = fminf(dr[2 * j],     dlo);
            float nd1 = fminf(dr[2 * j + 1], dhi);
            dr[2 * j] = nd0; dr[2 * j + 1] = nd1;
            mx = fmaxf(mx, fmaxf(nd0, nd1));
        }

        // Phase 1: block max via warp redux + fire-and-forget smem atomicMax.
        unsigned vb = __float_as_uint(mx);           // monotone for mx >= 0
        unsigned m1 = __reduce_max_sync(0xFFFFFFFFu, vb);
        if (lane == 0) atomicMax(&vslot[buf], m1);   // no return value used
        __syncthreads();                              // bar1 (drains atomics)
        unsigned m2 = vslot[buf];                     // broadcast LDS

        // Reset the *other* parity's fslot (its readers all passed bar1).
        if (tid == 0) fslot[buf ^ 1] = 0xFFFFFFFFu;

        // Phase 2: only warps holding the max recover the index.
        if (m1 == m2) {
            unsigned msk = 0;
            #pragma unroll
            for (int k = 0; k < PPT; k++)
                msk |= (__float_as_uint(dr[k]) == m2) ? (1u << k) : 0u;
            if (msk) {
                int k = __ffs(msk) - 1;               // lowest k -> lowest idx
                atomicMin(&fslot[buf], (unsigned)(tid + k * TT));
            }
        }
        __syncthreads();                              // bar2 (drains atomics)
        far = fslot[buf];                             // broadcast LDS
        if (tid == 0) vslot[buf] = 0u;                // reset for iter m+2
    }
}

extern "C" __global__ void gather_kernel(const float* __restrict__ feats,  // [B, C, N]
                                         float* __restrict__ out_feats)   // [B, M, C]
{
    int bm = blockIdx.x;                 // b * MM + m
    int b  = bm >> 11;                   // MM = 2048
    int n  = g_idx[bm];
    int c  = threadIdx.x;                // 0..CC-1
    out_feats[(size_t)bm * CC + c] = feats[((size_t)b * CC + c) * NN + n];
}

// Empty kernel: shifts ncu's "-s 5 -c 1" capture window onto fps_kernel
// (launch index 5 of the correctness call) so the FPS loop gets profiled.
extern "C" __global__ void warm_kernel() {}

extern "C" void kernel_launch(void* const* d_in, const int* in_sizes, int n_in,
                              void* d_out, int out_size)
{
    const float* pts   = (const float*)d_in[0];  // [B, 3, N]
    const float* feats = (const float*)d_in[1];  // [B, C, N]
    float* out = (float*)d_out;

    cudaFuncSetAttribute(fps_kernel,
                         cudaFuncAttributeMaxDynamicSharedMemorySize, SMEM_BYTES);

    warm_kernel<<<1, 1>>>();
    warm_kernel<<<1, 1>>>();
    warm_kernel<<<1, 1>>>();
    warm_kernel<<<1, 1>>>();
    warm_kernel<<<1, 1>>>();
    fps_kernel<<<BB, TT, SMEM_BYTES>>>(pts, out);
    gather_kernel<<<BB * MM, CC>>>(feats, out + (size_t)BB * MM * 3);
}

// round 6
// speedup vs baseline: 1.2333x; 1.2333x over previous
#include <cuda_runtime.h>

// Problem constants (fixed: B=16, N=8192, C=256, num_points=2048)
#define BB   16
#define NN   8192
#define CC   256
#define MM   2048
#define TT   1024          // threads per FPS block
#define PPT  (NN / TT)     // points per thread = 8
#define NPAIR (PPT / 2)    // f32x2 pairs per thread = 4

// Scratch: selected indices, written by FPS kernel, read by gather kernel.
__device__ int g_idx[BB * MM];

// Dynamic smem: sq4[NN] (float4) + pv[64] + pi[64] + cent[96]
#define SMEM_BYTES (NN * 16 + 64 * 4 + 64 * 4 + 96 * 4)

// ---- packed f32x2 helpers (sm_103a) ---------------------------------------
__device__ __forceinline__ unsigned long long pack2(float lo, float hi) {
    unsigned long long r;
    asm("mov.b64 %0, {%1, %2};" : "=l"(r) : "f"(lo), "f"(hi));
    return r;
}
__device__ __forceinline__ void unpack2(unsigned long long v, float& lo, float& hi) {
    asm("mov.b64 {%0, %1}, %2;" : "=f"(lo), "=f"(hi) : "l"(v));
}
__device__ __forceinline__ unsigned long long add2(unsigned long long a, unsigned long long b) {
    unsigned long long r;
    asm("add.rn.f32x2 %0, %1, %2;" : "=l"(r) : "l"(a), "l"(b));
    return r;
}
__device__ __forceinline__ unsigned long long mul2(unsigned long long a, unsigned long long b) {
    unsigned long long r;
    asm("mul.rn.f32x2 %0, %1, %2;" : "=l"(r) : "l"(a), "l"(b));
    return r;
}
// ---------------------------------------------------------------------------

__device__ __forceinline__ float warp_sum(float x) {
    #pragma unroll
    for (int o = 16; o > 0; o >>= 1)
        x += __shfl_xor_sync(0xFFFFFFFFu, x, o);
    return x;
}

extern "C" __global__ void __launch_bounds__(TT, 1)
fps_kernel(const float* __restrict__ pts,   // [B, 3, N]
           float* __restrict__ out_pts)     // [B, M, 3]
{
    extern __shared__ unsigned char smraw[];
    float4*   sq4  = (float4*)smraw;                 // [NN] (x,y,z,0)
    unsigned* pv   = (unsigned*)(smraw + NN * 16);   // [64] double-buffered
    unsigned* pi   = pv + 64;                        // [64] double-buffered
    float*    cent = (float*)(pi + 64);              // [96]

    const int b    = blockIdx.x;
    const int tid  = threadIdx.x;
    const int lane = tid & 31;
    const int warp = tid >> 5;

    const float* px = pts + (size_t)b * 3 * NN;
    const float* py = px + NN;
    const float* pz = px + 2 * NN;

    // Packed coords: pair j holds points (tid + 2j*TT, tid + (2j+1)*TT).
    unsigned long long X2[NPAIR], Y2[NPAIR], Z2[NPAIR];
    float dr[PPT];
    float s1 = 0.f, s2 = 0.f, s3 = 0.f;
    float xs[PPT], ys[PPT], zs[PPT];
    #pragma unroll
    for (int k = 0; k < PPT; k++) {
        int n = tid + k * TT;               // coalesced
        float x = px[n], y = py[n], z = pz[n];
        xs[k] = x; ys[k] = y; zs[k] = z;
        sq4[n] = make_float4(x, y, z, 0.f);
        s1 += x; s2 += y; s3 += z;
        dr[k] = 1e10f;
    }
    #pragma unroll
    for (int j = 0; j < NPAIR; j++) {
        X2[j] = pack2(xs[2 * j], xs[2 * j + 1]);
        Y2[j] = pack2(ys[2 * j], ys[2 * j + 1]);
        Z2[j] = pack2(zs[2 * j], zs[2 * j + 1]);
    }

    // Deterministic centroid (exact, one-shot).
    s1 = warp_sum(s1); s2 = warp_sum(s2); s3 = warp_sum(s3);
    if (lane == 0) { cent[warp] = s1; cent[32 + warp] = s2; cent[64 + warp] = s3; }
    __syncthreads();
    float cx = warp_sum(cent[lane])      * (1.0f / NN);
    float cy = warp_sum(cent[32 + lane]) * (1.0f / NN);
    float cz = warp_sum(cent[64 + lane]) * (1.0f / NN);

    // d0 = ||p - centroid||^2, initial farthest (exact plain form, one-shot).
    float best = -1.0f; unsigned bi = 0;
    #pragma unroll
    for (int k = 0; k < PPT; k++) {
        float dx = xs[k] - cx, dy = ys[k] - cy, dz = zs[k] - cz;
        float d = __fadd_rn(__fadd_rn(__fmul_rn(dx, dx), __fmul_rn(dy, dy)),
                            __fmul_rn(dz, dz));
        if (d > best) { best = d; bi = (unsigned)(tid + k * TT); }
    }
    {
        unsigned vb = __float_as_uint(best);
        unsigned m1 = __reduce_max_sync(0xFFFFFFFFu, vb);
        unsigned c1 = (vb == m1) ? bi : 0xFFFFFFFFu;
        unsigned i1 = __reduce_min_sync(0xFFFFFFFFu, c1);
        if (lane == 0) { pv[32 + warp] = m1; pi[32 + warp] = i1; }
    }
    __syncthreads();
    unsigned far;
    {
        unsigned v2 = pv[32 + lane];
        unsigned i2 = pi[32 + lane];
        unsigned m2 = __reduce_max_sync(0xFFFFFFFFu, v2);
        unsigned c2 = (v2 == m2) ? i2 : 0xFFFFFFFFu;
        far = __reduce_min_sync(0xFFFFFFFFu, c2);
    }

    float* outp = out_pts + (size_t)b * MM * 3;
    int*   idxp = g_idx + b * MM;

    for (int m = 0; m < MM; m++) {
        const int buf = m & 1;
        // Broadcast the selected point (one LDS.128, conflict-free broadcast).
        float4 q = sq4[far];
        if (tid == 0) {
            idxp[m] = (int)far;
            outp[m * 3 + 0] = q.x;
            outp[m * 3 + 1] = q.y;
            outp[m * 3 + 2] = q.z;
        }
        // Packed negated query (x - q == x + (-q), exact; rounding identical
        // to the reference's elementwise subtract/square/sum).
        unsigned long long nqx2 = pack2(-q.x, -q.x);
        unsigned long long nqy2 = pack2(-q.y, -q.y);
        unsigned long long nqz2 = pack2(-q.z, -q.z);

        #pragma unroll
        for (int j = 0; j < NPAIR; j++) {
            unsigned long long dx2 = add2(X2[j], nqx2);
            unsigned long long dy2 = add2(Y2[j], nqy2);
            unsigned long long dz2 = add2(Z2[j], nqz2);
            // d = (dx*dx + dy*dy) + dz*dz, RN per lane, no contraction:
            unsigned long long d2 = add2(add2(mul2(dx2, dx2), mul2(dy2, dy2)),
                                         mul2(dz2, dz2));
            float dlo, dhi;
            unpack2(d2, dlo, dhi);
            dr[2 * j]     = fminf(dr[2 * j],     dlo);
            dr[2 * j + 1] = fminf(dr[2 * j + 1], dhi);
        }
        // Per-thread max as a balanced tree over dr (ILP, one fewer op).
        float a0 = fmaxf(dr[0], dr[1]);
        float a1 = fmaxf(dr[2], dr[3]);
        float a2 = fmaxf(dr[4], dr[5]);
        float a3 = fmaxf(dr[6], dr[7]);
        float mx = fmaxf(fmaxf(a0, a1), fmaxf(a2, a3));

        // Phase 1: value-only block max (distances nonneg in exact form).
        unsigned vb = __float_as_uint(mx);
        unsigned m1 = __reduce_max_sync(0xFFFFFFFFu, vb);
        if (lane == 0) pv[buf * 32 + warp] = m1;
        __syncthreads();                              // bar1
        unsigned m2 = __reduce_max_sync(0xFFFFFFFFu, pv[buf * 32 + lane]);

        // Phase 2: only winning warp(s) recover the index (bit-equality scan;
        // global idx = tid + k*1024, so numeric min == first-index tie-break).
        unsigned cand = 0xFFFFFFFFu;
        if (m1 == m2) {
            #pragma unroll
            for (int k = PPT - 1; k >= 0; k--)        // descending k -> lowest idx
                if (__float_as_uint(dr[k]) == m2) cand = (unsigned)(tid + k * TT);
            cand = __reduce_min_sync(0xFFFFFFFFu, cand);
        }
        if (lane == 0) pi[buf * 32 + warp] = cand;
        __syncthreads();                              // bar2
        far = __reduce_min_sync(0xFFFFFFFFu, pi[buf * 32 + lane]);
    }
}

// Gather with channel-tiled blocks: block = (b, ctile of 32 channels, mtile of
// 512 samples). Indices preloaded to smem; reads of each 32KB channel plane get
// L1/L2 reuse across the 512 m's; writes stay 128B-coalesced per (warp, m).
#define CT 32            // channels per block
#define MT 512           // samples per block
extern "C" __global__ void __launch_bounds__(256)
gather_kernel(const float* __restrict__ feats,  // [B, C, N]
              float* __restrict__ out_feats)    // [B, M, C]
{
    __shared__ int sn[MT];
    int blk = blockIdx.x;                    // b * 32 + ct * 4 + mt
    int b   = blk >> 5;
    int ct  = (blk >> 2) & 7;                // 8 channel tiles
    int mt  = blk & 3;                       // 4 sample tiles
    int tid = threadIdx.x;

    for (int i = tid; i < MT; i += 256)
        sn[i] = g_idx[b * MM + mt * MT + i];
    __syncthreads();

    int c  = ct * CT + (tid & 31);
    int ml = tid >> 5;                       // 0..7
    const float* fp = feats + ((size_t)b * CC + c) * NN;
    float* op = out_feats + ((size_t)b * MM + mt * MT) * CC + c;

    #pragma unroll 4
    for (int mm = ml; mm < MT; mm += 8)
        op[(size_t)mm * CC] = fp[sn[mm]];
}

// Tiny kernel to align ncu's "-s 5 -c 1" window onto fps_kernel.
extern "C" __global__ void warm_kernel() {}

extern "C" void kernel_launch(void* const* d_in, const int* in_sizes, int n_in,
                              void* d_out, int out_size)
{
    const float* pts   = (const float*)d_in[0];  // [B, 3, N]
    const float* feats = (const float*)d_in[1];  // [B, C, N]
    float* out = (float*)d_out;

    cudaFuncSetAttribute(fps_kernel,
                         cudaFuncAttributeMaxDynamicSharedMemorySize, SMEM_BYTES);

    fps_kernel<<<BB, TT, SMEM_BYTES>>>(pts, out);
    warm_kernel<<<1, 1>>>();
    gather_kernel<<<BB * 32, 256>>>(feats, out + (size_t)BB * MM * 3);
}

// round 7
// speedup vs baseline: 1.3827x; 1.1212x over previous
#include <cuda_runtime.h>

// Problem constants (fixed: B=16, N=8192, C=256, num_points=2048)
#define BB   16
#define NN   8192
#define CC   256
#define MM   2048
#define TT   1024          // threads per FPS block
#define PPT  (NN / TT)     // points per thread = 8
#define NPAIR (PPT / 2)    // f32x2 pairs per thread = 4

// Scratch: selected indices, written by FPS kernel, read by gather kernel.
__device__ int g_idx[BB * MM];

// Dynamic smem: sq4[NN] float4 | pv[64] | pi[64] | cent[96] | kx[NN] | ki[NN]
#define SMEM_BYTES (NN * 16 + 64 * 4 + 64 * 4 + 96 * 4 + NN * 4 + NN * 4)

// ---- packed f32x2 helpers (sm_103a) ---------------------------------------
__device__ __forceinline__ unsigned long long pack2(float lo, float hi) {
    unsigned long long r;
    asm("mov.b64 %0, {%1, %2};" : "=l"(r) : "f"(lo), "f"(hi));
    return r;
}
__device__ __forceinline__ void unpack2(unsigned long long v, float& lo, float& hi) {
    asm("mov.b64 {%0, %1}, %2;" : "=f"(lo), "=f"(hi) : "l"(v));
}
__device__ __forceinline__ unsigned long long add2(unsigned long long a, unsigned long long b) {
    unsigned long long r;
    asm("add.rn.f32x2 %0, %1, %2;" : "=l"(r) : "l"(a), "l"(b));
    return r;
}
__device__ __forceinline__ unsigned long long mul2(unsigned long long a, unsigned long long b) {
    unsigned long long r;
    asm("mul.rn.f32x2 %0, %1, %2;" : "=l"(r) : "l"(a), "l"(b));
    return r;
}
// ---------------------------------------------------------------------------

__device__ __forceinline__ float warp_sum(float x) {
    #pragma unroll
    for (int o = 16; o > 0; o >>= 1)
        x += __shfl_xor_sync(0xFFFFFFFFu, x, o);
    return x;
}
__device__ __forceinline__ float warp_min(float x) {
    #pragma unroll
    for (int o = 16; o > 0; o >>= 1)
        x = fminf(x, __shfl_xor_sync(0xFFFFFFFFu, x, o));
    return x;
}
__device__ __forceinline__ float warp_max(float x) {
    #pragma unroll
    for (int o = 16; o > 0; o >>= 1)
        x = fmaxf(x, __shfl_xor_sync(0xFFFFFFFFu, x, o));
    return x;
}

extern "C" __global__ void __launch_bounds__(TT, 1)
fps_kernel(const float* __restrict__ pts,   // [B, 3, N]
           float* __restrict__ out_pts)     // [B, M, 3]
{
    extern __shared__ unsigned char smraw[];
    float4*   sq4  = (float4*)smraw;                 // [NN] orig-indexed coords
    unsigned* pv   = (unsigned*)(smraw + NN * 16);   // [64] double-buffered
    unsigned* pi   = pv + 64;                        // [64] double-buffered
    float*    cent = (float*)(pi + 64);              // [96]
    float*    skx  = cent + 96;                      // [NN] sort keys (x)
    int*      ski  = (int*)(skx + NN);               // [NN] orig indices

    const int b    = blockIdx.x;
    const int tid  = threadIdx.x;
    const int lane = tid & 31;
    const int warp = tid >> 5;

    const float* px = pts + (size_t)b * 3 * NN;
    const float* py = px + NN;
    const float* pz = px + 2 * NN;

    // ---- load (orig layout), centroid sums, sort-key init ----
    float s1 = 0.f, s2 = 0.f, s3 = 0.f;
    #pragma unroll
    for (int k = 0; k < PPT; k++) {
        int n = tid + k * TT;               // coalesced
        float x = px[n], y = py[n], z = pz[n];
        sq4[n] = make_float4(x, y, z, 0.f);
        skx[n] = x; ski[n] = n;
        s1 += x; s2 += y; s3 += z;
    }

    // Deterministic centroid (exact, one-shot).
    s1 = warp_sum(s1); s2 = warp_sum(s2); s3 = warp_sum(s3);
    if (lane == 0) { cent[warp] = s1; cent[32 + warp] = s2; cent[64 + warp] = s3; }

    // ---- bitonic sort by x (permutation-preserving; quality only affects
    //      pruning, never correctness) ----
    for (int k = 2; k <= NN; k <<= 1) {
        for (int j = k >> 1; j > 0; j >>= 1) {
            __syncthreads();
            #pragma unroll 4
            for (int t = tid; t < NN / 2; t += TT) {
                int i = 2 * t - (t & (j - 1));
                int l = i + j;
                bool up = ((i & k) == 0);
                float a = skx[i], c = skx[l];
                bool sw = up ? (a > c) : (a < c);
                if (sw) {
                    skx[i] = c; skx[l] = a;
                    int ta = ski[i]; ski[i] = ski[l]; ski[l] = ta;
                }
            }
        }
    }
    __syncthreads();

    // ---- reorder into registers: warp w owns sorted ranks [256w, 256w+256) ----
    unsigned long long X2[NPAIR], Y2[NPAIR], Z2[NPAIR];
    unsigned OI2[NPAIR];                    // packed orig indices (lo | hi<<16)
    float dr[PPT];
    float xs[PPT], ys[PPT], zs[PPT];
    unsigned oi[PPT];
    const int base = warp * 256 + lane;
    #pragma unroll
    for (int k = 0; k < PPT; k++) {
        int r = base + 32 * k;
        int idx = ski[r];
        float4 p = sq4[idx];
        xs[k] = p.x; ys[k] = p.y; zs[k] = p.z;
        oi[k] = (unsigned)idx;
        dr[k] = 1e10f;
    }
    #pragma unroll
    for (int j = 0; j < NPAIR; j++) {
        X2[j] = pack2(xs[2 * j], xs[2 * j + 1]);
        Y2[j] = pack2(ys[2 * j], ys[2 * j + 1]);
        Z2[j] = pack2(zs[2 * j], zs[2 * j + 1]);
        OI2[j] = oi[2 * j] | (oi[2 * j + 1] << 16);
    }
    // Warp x-extent (from the points this warp actually holds).
    float xmn = xs[0], xmx = xs[0];
    #pragma unroll
    for (int k = 1; k < PPT; k++) { xmn = fminf(xmn, xs[k]); xmx = fmaxf(xmx, xs[k]); }
    xmn = warp_min(xmn); xmx = warp_max(xmx);

    // Centroid finalize.
    float cx = warp_sum(cent[lane])      * (1.0f / NN);
    float cy = warp_sum(cent[32 + lane]) * (1.0f / NN);
    float cz = warp_sum(cent[64 + lane]) * (1.0f / NN);

    // d0 = ||p - centroid||^2, initial farthest (exact plain form; orig-idx
    // tie-break since held points are no longer index-ordered).
    float best = -1.0f; unsigned bi = 0xFFFFFFFFu;
    #pragma unroll
    for (int k = 0; k < PPT; k++) {
        float dx = xs[k] - cx, dy = ys[k] - cy, dz = zs[k] - cz;
        float d = __fadd_rn(__fadd_rn(__fmul_rn(dx, dx), __fmul_rn(dy, dy)),
                            __fmul_rn(dz, dz));
        if (d > best)            { best = d; bi = oi[k]; }
        else if (d == best && oi[k] < bi) bi = oi[k];
    }
    {
        unsigned vb = __float_as_uint(best);
        unsigned m1 = __reduce_max_sync(0xFFFFFFFFu, vb);
        unsigned c1 = (vb == m1) ? bi : 0xFFFFFFFFu;
        unsigned i1 = __reduce_min_sync(0xFFFFFFFFu, c1);
        if (lane == 0) { pv[32 + warp] = m1; pi[32 + warp] = i1; }
    }
    __syncthreads();
    unsigned far;
    {
        unsigned v2 = pv[32 + lane];
        unsigned i2 = pi[32 + lane];
        unsigned m2 = __reduce_max_sync(0xFFFFFFFFu, v2);
        unsigned c2 = (v2 == m2) ? i2 : 0xFFFFFFFFu;
        far = __reduce_min_sync(0xFFFFFFFFu, c2);
    }

    float* outp = out_pts + (size_t)b * MM * 3;
    int*   idxp = g_idx + b * MM;

    unsigned wvb = __float_as_uint(1e10f);   // warp's exact max dr (bits, uniform)

    for (int m = 0; m < MM; m++) {
        const int buf = m & 1;
        // Broadcast the selected point (one LDS.128, orig-indexed table).
        float4 q = sq4[far];
        if (tid == 0) {
            idxp[m] = (int)far;
            outp[m * 3 + 0] = q.x;
            outp[m * 3 + 1] = q.y;
            outp[m * 3 + 2] = q.z;
        }

        // Slab prune: if 0.99999*gap_x^2 >= wmax, the min-update is a no-op
        // for every point this warp holds (d >= dx^2 up to < 1e-5 rel slack).
        float gap = fmaxf(fmaxf(xmn - q.x, q.x - xmx), 0.0f);
        float bnd = __fmul_rn(__fmul_rn(gap, gap), 0.99999f);
        if (bnd < __uint_as_float(wvb)) {
            // Exact update (reference-rounded, no contraction).
            unsigned long long nqx2 = pack2(-q.x, -q.x);
            unsigned long long nqy2 = pack2(-q.y, -q.y);
            unsigned long long nqz2 = pack2(-q.z, -q.z);
            #pragma unroll
            for (int j = 0; j < NPAIR; j++) {
                unsigned long long dx2 = add2(X2[j], nqx2);
                unsigned long long dy2 = add2(Y2[j], nqy2);
                unsigned long long dz2 = add2(Z2[j], nqz2);
                unsigned long long d2 = add2(add2(mul2(dx2, dx2), mul2(dy2, dy2)),
                                             mul2(dz2, dz2));
                float dlo, dhi;
                unpack2(d2, dlo, dhi);
                dr[2 * j]     = fminf(dr[2 * j],     dlo);
                dr[2 * j + 1] = fminf(dr[2 * j + 1], dhi);
            }
            float a0 = fmaxf(dr[0], dr[1]);
            float a1 = fmaxf(dr[2], dr[3]);
            float a2 = fmaxf(dr[4], dr[5]);
            float a3 = fmaxf(dr[6], dr[7]);
            float mx = fmaxf(fmaxf(a0, a1), fmaxf(a2, a3));
            wvb = __reduce_max_sync(0xFFFFFFFFu, __float_as_uint(mx));
        }
        // (skipped warps keep exact dr and exact wvb)

        if (lane == 0) pv[buf * 32 + warp] = wvb;
        __syncthreads();                              // bar1
        unsigned m2 = __reduce_max_sync(0xFFFFFFFFu, pv[buf * 32 + lane]);

        // Phase 2: winning warp(s) recover min ORIGINAL index among bit-equal.
        unsigned cand = 0xFFFFFFFFu;
        if (wvb == m2) {
            #pragma unroll
            for (int j = 0; j < NPAIR; j++) {
                if (__float_as_uint(dr[2 * j])     == m2)
                    cand = min(cand, OI2[j] & 0xFFFFu);
                if (__float_as_uint(dr[2 * j + 1]) == m2)
                    cand = min(cand, OI2[j] >> 16);
            }
            cand = __reduce_min_sync(0xFFFFFFFFu, cand);
        }
        if (lane == 0) pi[buf * 32 + warp] = cand;
        __syncthreads();                              // bar2
        far = __reduce_min_sync(0xFFFFFFFFu, pi[buf * 32 + lane]);
    }
}

// Gather with channel-tiled blocks (indices preloaded to smem; coalesced
// writes; channel-plane reads get L1/L2 reuse).
#define CT 32            // channels per block
#define MT 512           // samples per block
extern "C" __global__ void __launch_bounds__(256)
gather_kernel(const float* __restrict__ feats,  // [B, C, N]
              float* __restrict__ out_feats)    // [B, M, C]
{
    __shared__ int sn[MT];
    int blk = blockIdx.x;                    // b * 32 + ct * 4 + mt
    int b   = blk >> 5;
    int ct  = (blk >> 2) & 7;                // 8 channel tiles
    int mt  = blk & 3;                       // 4 sample tiles
    int tid = threadIdx.x;

    for (int i = tid; i < MT; i += 256)
        sn[i] = g_idx[b * MM + mt * MT + i];
    __syncthreads();

    int c  = ct * CT + (tid & 31);
    int ml = tid >> 5;                       // 0..7
    const float* fp = feats + ((size_t)b * CC + c) * NN;
    float* op = out_feats + ((size_t)b * MM + mt * MT) * CC + c;

    #pragma unroll 4
    for (int mm = ml; mm < MT; mm += 8)
        op[(size_t)mm * CC] = fp[sn[mm]];
}

// Tiny kernel to keep ncu's "-s 5 -c 1" window on fps_kernel.
extern "C" __global__ void warm_kernel() {}

extern "C" void kernel_launch(void* const* d_in, const int* in_sizes, int n_in,
                              void* d_out, int out_size)
{
    const float* pts   = (const float*)d_in[0];  // [B, 3, N]
    const float* feats = (const float*)d_in[1];  // [B, C, N]
    float* out = (float*)d_out;

    cudaFuncSetAttribute(fps_kernel,
                         cudaFuncAttributeMaxDynamicSharedMemorySize, SMEM_BYTES);

    fps_kernel<<<BB, TT, SMEM_BYTES>>>(pts, out);
    warm_kernel<<<1, 1>>>();
    gather_kernel<<<BB * 32, 256>>>(feats, out + (size_t)BB * MM * 3);
}

// round 8
// speedup vs baseline: 1.4197x; 1.0267x over previous
#include <cuda_runtime.h>

// Problem constants (fixed: B=16, N=8192, C=256, num_points=2048)
#define BB   16
#define NN   8192
#define CC   256
#define MM   2048
#define TT   1024          // threads per FPS block
#define PPT  (NN / TT)     // points per thread = 8
#define NPAIR (PPT / 2)    // f32x2 pairs per thread = 4

// Scratch: selected indices, written by FPS kernel, read by gather kernel.
__device__ int g_idx[BB * MM];

// Dynamic smem: sq4[NN] float4 | pvi[64] uint2 | initv[32] | initi[32] |
//               cent[96] | skx[NN] | ski[NN]
#define SMEM_BYTES (NN * 16 + 64 * 8 + 32 * 4 + 32 * 4 + 96 * 4 + NN * 4 + NN * 4)

// ---- packed f32x2 helpers (sm_103a) ---------------------------------------
__device__ __forceinline__ unsigned long long pack2(float lo, float hi) {
    unsigned long long r;
    asm("mov.b64 %0, {%1, %2};" : "=l"(r) : "f"(lo), "f"(hi));
    return r;
}
__device__ __forceinline__ void unpack2(unsigned long long v, float& lo, float& hi) {
    asm("mov.b64 {%0, %1}, %2;" : "=f"(lo), "=f"(hi) : "l"(v));
}
__device__ __forceinline__ unsigned long long add2(unsigned long long a, unsigned long long b) {
    unsigned long long r;
    asm("add.rn.f32x2 %0, %1, %2;" : "=l"(r) : "l"(a), "l"(b));
    return r;
}
__device__ __forceinline__ unsigned long long mul2(unsigned long long a, unsigned long long b) {
    unsigned long long r;
    asm("mul.rn.f32x2 %0, %1, %2;" : "=l"(r) : "l"(a), "l"(b));
    return r;
}
// ---------------------------------------------------------------------------

__device__ __forceinline__ float warp_sum(float x) {
    #pragma unroll
    for (int o = 16; o > 0; o >>= 1)
        x += __shfl_xor_sync(0xFFFFFFFFu, x, o);
    return x;
}
__device__ __forceinline__ float warp_min(float x) {
    #pragma unroll
    for (int o = 16; o > 0; o >>= 1)
        x = fminf(x, __shfl_xor_sync(0xFFFFFFFFu, x, o));
    return x;
}
__device__ __forceinline__ float warp_max(float x) {
    #pragma unroll
    for (int o = 16; o > 0; o >>= 1)
        x = fmaxf(x, __shfl_xor_sync(0xFFFFFFFFu, x, o));
    return x;
}

extern "C" __global__ void __launch_bounds__(TT, 1)
fps_kernel(const float* __restrict__ pts,   // [B, 3, N]
           float* __restrict__ out_pts)     // [B, M, 3]
{
    extern __shared__ unsigned char smraw[];
    float4*   sq4   = (float4*)smraw;                  // [NN] orig-indexed coords
    uint2*    pvi   = (uint2*)(smraw + NN * 16);       // [64] (val,cand), 2 bufs
    unsigned* initv = (unsigned*)(pvi + 64);           // [32]
    unsigned* initi = initv + 32;                      // [32]
    float*    cent  = (float*)(initi + 32);            // [96]
    float*    skx   = cent + 96;                       // [NN] sort keys (x)
    int*      ski   = (int*)(skx + NN);                // [NN] orig indices

    const int b    = blockIdx.x;
    const int tid  = threadIdx.x;
    const int lane = tid & 31;
    const int warp = tid >> 5;

    const float* px = pts + (size_t)b * 3 * NN;
    const float* py = px + NN;
    const float* pz = px + 2 * NN;

    // ---- load (orig layout), centroid sums, sort-key init ----
    float s1 = 0.f, s2 = 0.f, s3 = 0.f;
    #pragma unroll
    for (int k = 0; k < PPT; k++) {
        int n = tid + k * TT;               // coalesced
        float x = px[n], y = py[n], z = pz[n];
        sq4[n] = make_float4(x, y, z, 0.f);
        skx[n] = x; ski[n] = n;
        s1 += x; s2 += y; s3 += z;
    }

    // Deterministic centroid (exact, one-shot).
    s1 = warp_sum(s1); s2 = warp_sum(s2); s3 = warp_sum(s3);
    if (lane == 0) { cent[warp] = s1; cent[32 + warp] = s2; cent[64 + warp] = s3; }

    // ---- bitonic sort by x (permutation-preserving; quality only affects
    //      pruning, never correctness) ----
    for (int k = 2; k <= NN; k <<= 1) {
        for (int j = k >> 1; j > 0; j >>= 1) {
            __syncthreads();
            #pragma unroll 4
            for (int t = tid; t < NN / 2; t += TT) {
                int i = 2 * t - (t & (j - 1));
                int l = i + j;
                bool up = ((i & k) == 0);
                float a = skx[i], c = skx[l];
                bool sw = up ? (a > c) : (a < c);
                if (sw) {
                    skx[i] = c; skx[l] = a;
                    int ta = ski[i]; ski[i] = ski[l]; ski[l] = ta;
                }
            }
        }
    }
    __syncthreads();

    // ---- reorder into registers: warp w owns sorted ranks [256w, 256w+256) ----
    unsigned long long X2[NPAIR], Y2[NPAIR], Z2[NPAIR];
    unsigned OI2[NPAIR];                    // packed orig indices (lo | hi<<16)
    float dr[PPT];
    float xs[PPT], ys[PPT], zs[PPT];
    unsigned oi[PPT];
    const int base = warp * 256 + lane;
    #pragma unroll
    for (int k = 0; k < PPT; k++) {
        int r = base + 32 * k;
        int idx = ski[r];
        float4 p = sq4[idx];
        xs[k] = p.x; ys[k] = p.y; zs[k] = p.z;
        oi[k] = (unsigned)idx;
        dr[k] = 1e10f;
    }
    #pragma unroll
    for (int j = 0; j < NPAIR; j++) {
        X2[j] = pack2(xs[2 * j], xs[2 * j + 1]);
        Y2[j] = pack2(ys[2 * j], ys[2 * j + 1]);
        Z2[j] = pack2(zs[2 * j], zs[2 * j + 1]);
        OI2[j] = oi[2 * j] | (oi[2 * j + 1] << 16);
    }
    // Warp x-extent (from the points this warp actually holds).
    float xmn = xs[0], xmx = xs[0];
    #pragma unroll
    for (int k = 1; k < PPT; k++) { xmn = fminf(xmn, xs[k]); xmx = fmaxf(xmx, xs[k]); }
    xmn = warp_min(xmn); xmx = warp_max(xmx);

    // Centroid finalize.
    float cx = warp_sum(cent[lane])      * (1.0f / NN);
    float cy = warp_sum(cent[32 + lane]) * (1.0f / NN);
    float cz = warp_sum(cent[64 + lane]) * (1.0f / NN);

    // d0 = ||p - centroid||^2, initial farthest (exact plain form; orig-idx
    // tie-break since held points are no longer index-ordered).
    float best = -1.0f; unsigned bi = 0xFFFFFFFFu;
    #pragma unroll
    for (int k = 0; k < PPT; k++) {
        float dx = xs[k] - cx, dy = ys[k] - cy, dz = zs[k] - cz;
        float d = __fadd_rn(__fadd_rn(__fmul_rn(dx, dx), __fmul_rn(dy, dy)),
                            __fmul_rn(dz, dz));
        if (d > best)            { best = d; bi = oi[k]; }
        else if (d == best && oi[k] < bi) bi = oi[k];
    }
    {
        unsigned vb = __float_as_uint(best);
        unsigned m1 = __reduce_max_sync(0xFFFFFFFFu, vb);
        unsigned c1 = (vb == m1) ? bi : 0xFFFFFFFFu;
        unsigned i1 = __reduce_min_sync(0xFFFFFFFFu, c1);
        if (lane == 0) { initv[warp] = m1; initi[warp] = i1; }
    }
    __syncthreads();
    unsigned far;
    {
        unsigned v2 = initv[lane];
        unsigned i2 = initi[lane];
        unsigned m2 = __reduce_max_sync(0xFFFFFFFFu, v2);
        unsigned c2 = (v2 == m2) ? i2 : 0xFFFFFFFFu;
        far = __reduce_min_sync(0xFFFFFFFFu, c2);
    }

    float* outp = out_pts + (size_t)b * MM * 3;
    int*   idxp = g_idx + b * MM;

    // Per-warp cached state: exact max-dr bits + min orig idx among ties.
    // Valid while the warp skips updates (dr unchanged). First iteration
    // always updates (bnd < 1e10), which initializes wcand properly.
    unsigned wvb   = __float_as_uint(1e10f);
    unsigned wcand = 0xFFFFFFFFu;

    for (int m = 0; m < MM; m++) {
        const int buf = m & 1;
        // Broadcast the selected point (one LDS.128, orig-indexed table).
        float4 q = sq4[far];
        if (tid == 0) {
            idxp[m] = (int)far;
            outp[m * 3 + 0] = q.x;
            outp[m * 3 + 1] = q.y;
            outp[m * 3 + 2] = q.z;
        }

        // Slab prune: if 0.99999*gap_x^2 >= warp max dr, the min-update is a
        // no-op for every point this warp holds -> dr, wvb, wcand all keep
        // their exact values and the warp just joins the reduction.
        float gap = fmaxf(fmaxf(xmn - q.x, q.x - xmx), 0.0f);
        float bnd = __fmul_rn(__fmul_rn(gap, gap), 0.99999f);
        if (bnd < __uint_as_float(wvb)) {
            // Exact update (reference-rounded, no contraction).
            unsigned long long nqx2 = pack2(-q.x, -q.x);
            unsigned long long nqy2 = pack2(-q.y, -q.y);
            unsigned long long nqz2 = pack2(-q.z, -q.z);
            #pragma unroll
            for (int j = 0; j < NPAIR; j++) {
                unsigned long long dx2 = add2(X2[j], nqx2);
                unsigned long long dy2 = add2(Y2[j], nqy2);
                unsigned long long dz2 = add2(Z2[j], nqz2);
                unsigned long long d2 = add2(add2(mul2(dx2, dx2), mul2(dy2, dy2)),
                                             mul2(dz2, dz2));
                float dlo, dhi;
                unpack2(d2, dlo, dhi);
                dr[2 * j]     = fminf(dr[2 * j],     dlo);
                dr[2 * j + 1] = fminf(dr[2 * j + 1], dhi);
            }
            float a0 = fmaxf(dr[0], dr[1]);
            float a1 = fmaxf(dr[2], dr[3]);
            float a2 = fmaxf(dr[4], dr[5]);
            float a3 = fmaxf(dr[6], dr[7]);
            float mx = fmaxf(fmaxf(a0, a1), fmaxf(a2, a3));
            wvb = __reduce_max_sync(0xFFFFFFFFu, __float_as_uint(mx));
            // Min original index among bit-equal maxima (this warp).
            unsigned cand = 0xFFFFFFFFu;
            #pragma unroll
            for (int j = 0; j < NPAIR; j++) {
                if (__float_as_uint(dr[2 * j])     == wvb)
                    cand = min(cand, OI2[j] & 0xFFFFu);
                if (__float_as_uint(dr[2 * j + 1]) == wvb)
                    cand = min(cand, OI2[j] >> 16);
            }
            wcand = __reduce_min_sync(0xFFFFFFFFu, cand);
        }

        // Single-barrier block argmax over the 32 cached (wvb, wcand) pairs.
        if (lane == 0) pvi[buf * 32 + warp] = make_uint2(wvb, wcand);
        __syncthreads();
        uint2 p2 = pvi[buf * 32 + lane];                 // LDS.64
        unsigned m2 = __reduce_max_sync(0xFFFFFFFFu, p2.x);
        unsigned c2 = (p2.x == m2) ? p2.y : 0xFFFFFFFFu;
        far = __reduce_min_sync(0xFFFFFFFFu, c2);
    }
}

// Gather with channel-tiled blocks (indices preloaded to smem; coalesced
// writes; channel-plane reads get L1/L2 reuse).
#define CT 32            // channels per block
#define MT 512           // samples per block
extern "C" __global__ void __launch_bounds__(256)
gather_kernel(const float* __restrict__ feats,  // [B, C, N]
              float* __restrict__ out_feats)    // [B, M, C]
{
    __shared__ int sn[MT];
    int blk = blockIdx.x;                    // b * 32 + ct * 4 + mt
    int b   = blk >> 5;
    int ct  = (blk >> 2) & 7;                // 8 channel tiles
    int mt  = blk & 3;                       // 4 sample tiles
    int tid = threadIdx.x;

    for (int i = tid; i < MT; i += 256)
        sn[i] = g_idx[b * MM + mt * MT + i];
    __syncthreads();

    int c  = ct * CT + (tid & 31);
    int ml = tid >> 5;                       // 0..7
    const float* fp = feats + ((size_t)b * CC + c) * NN;
    float* op = out_feats + ((size_t)b * MM + mt * MT) * CC + c;

    #pragma unroll 4
    for (int mm = ml; mm < MT; mm += 8)
        op[(size_t)mm * CC] = fp[sn[mm]];
}

// Tiny kernel to keep ncu's "-s 5 -c 1" window on fps_kernel.
extern "C" __global__ void warm_kernel() {}

extern "C" void kernel_launch(void* const* d_in, const int* in_sizes, int n_in,
                              void* d_out, int out_size)
{
    const float* pts   = (const float*)d_in[0];  // [B, 3, N]
    const float* feats = (const float*)d_in[1];  // [B, C, N]
    float* out = (float*)d_out;

    cudaFuncSetAttribute(fps_kernel,
                         cudaFuncAttributeMaxDynamicSharedMemorySize, SMEM_BYTES);

    fps_kernel<<<BB, TT, SMEM_BYTES>>>(pts, out);
    warm_kernel<<<1, 1>>>();
    gather_kernel<<<BB * 32, 256>>>(feats, out + (size_t)BB * MM * 3);
}